// round 10
// baseline (speedup 1.0000x reference)
#include <cuda_runtime.h>
#include <cstdint>
#include <math.h>

#define NP 8192            // particles == channels
#define NWB (NP / 16)      // k_weights grid size (512 blocks)

// ---------------- device scratch (no allocations allowed) ----------------
__device__ float g_state[NP * 3];
__device__ float g_invw[NP];
__device__ float g_sum[3];
__device__ int   g_done;
__device__ int   g_wdone;   // k_weights completion counter (software flag)

// ---------------- threefry2x32 (JAX rotation schedule) -------------------
// Original all-SHF form (used by k_state; negligible cost there).
__device__ __forceinline__ uint32_t tf32(uint32_t k0, uint32_t k1, uint32_t n)
{
    uint32_t k2 = k0 ^ k1 ^ 0x1BD11BDAu;
    uint32_t x0 = k0;          // 0 + ks[0]
    uint32_t x1 = n + k1;      // n + ks[1]
#define TFR(r) { x0 += x1; x1 = __funnelshift_l(x1, x1, (r)); x1 ^= x0; }
    TFR(13) TFR(15) TFR(26) TFR(6)
    x0 += k1; x1 += k2 + 1u;
    TFR(17) TFR(29) TFR(16) TFR(24)
    x0 += k2; x1 += k0 + 2u;
    TFR(13) TFR(15) TFR(26) TFR(6)
    x0 += k0; x1 += k1 + 3u;
    TFR(17) TFR(29) TFR(16) TFR(24)
    x0 += k1; x1 += k2 + 4u;
    TFR(13) TFR(15) TFR(26) TFR(6)
    x0 += k2; x1 += k0 + 5u;
#undef TFR
    return x0 ^ x1;
}

// rotl(x, r) computed on the FMA pipe: mul.wide.u32(x, 1<<r) gives
// lo = x<<r, hi = x>>(32-r); (lo|hi) is the exact rotation (0<r<32).
// The caller's (lo|hi)^x0 fuses into a single LOP3.
__device__ __forceinline__ uint32_t rotmul(uint32_t x, uint32_t pow2r)
{
    uint32_t lo, hi;
    asm("{\n\t"
        ".reg .b64 t;\n\t"
        "mul.wide.u32 t, %2, %3;\n\t"
        "mov.b64 {%0, %1}, t;\n\t"
        "}" : "=r"(lo), "=r"(hi) : "r"(x), "r"(pow2r));
    return lo | hi;
}

// Pipe-balanced threefry: identical bits, half the rotations moved off the
// alu pipe (SHF) onto the fma pipe (IMAD.WIDE). alu-forced inst/elem drops
// from ~41 to ~31, breaking the alu-pipe bound.
__device__ __forceinline__ uint32_t tf32_bal(uint32_t k0, uint32_t k1, uint32_t n)
{
    uint32_t k2 = k0 ^ k1 ^ 0x1BD11BDAu;
    uint32_t x0 = k0;
    uint32_t x1 = n + k1;
#define TFA(r) { x0 += x1; x1 = __funnelshift_l(x1, x1, (r)); x1 ^= x0; }
#define TFB(r) { x0 += x1; x1 = rotmul(x1, 1u << (r)) ^ x0; }
    TFA(13) TFB(15) TFA(26) TFB(6)
    x0 += k1; x1 += k2 + 1u;
    TFA(17) TFB(29) TFA(16) TFB(24)
    x0 += k2; x1 += k0 + 2u;
    TFA(13) TFB(15) TFA(26) TFB(6)
    x0 += k0; x1 += k1 + 3u;
    TFA(17) TFB(29) TFA(16) TFB(24)
    x0 += k1; x1 += k2 + 4u;
    TFA(13) TFB(15) TFA(26) TFB(6)
    x0 += k2; x1 += k0 + 5u;
#undef TFA
#undef TFB
    return x0 ^ x1;
}

// exact v for the categorical: v = (-logf(u)) * invw, identical arithmetic
// to the validated round-1 kernel (bitwise-stable selection).
__device__ __forceinline__ float exact_v(uint32_t b, float invw)
{
    uint32_t tbits = __umulhi(b, 0x00800000u) + 0x3f800000u; // 1 + (b>>9)*2^-23
    float f = __uint_as_float(tbits) - 1.0f;
    float u = fmaxf(f, 1.17549435e-38f);
    float e = -logf(u);
    return e * invw;
}

// ---------------- kernel A: state transition + process noise -------------
__global__ void k_state(const float* __restrict__ sv,
                        const float* __restrict__ T,
                        const float* __restrict__ Q,
                        uint32_t kn0, uint32_t kn1)
{
    int p = blockIdx.x * blockDim.x + threadIdx.x;
    if (p < 3) g_sum[p] = 0.0f;   // reset accumulators each launch (graph replay)
    if (p == 3) g_done = 0;
    if (p == 4) g_wdone = 0;
    if (p >= NP) return;

    float l00 = sqrtf(Q[0]);
    float l10 = Q[3] / l00, l20 = Q[6] / l00;
    float l11 = sqrtf(Q[4] - l10 * l10);
    float l21 = (Q[7] - l20 * l10) / l11;
    float l22 = sqrtf(Q[8] - l20 * l20 - l21 * l21);

    float z[3];
#pragma unroll
    for (int d = 0; d < 3; ++d) {
        uint32_t b = tf32(kn0, kn1, (uint32_t)(3 * p + d));
        float f = __uint_as_float(0x3f800000u | (b >> 9)) - 1.0f;
        float val = __fadd_rn(__fmul_rn(f, 2.0f), -0.99999994f);
        val = fmaxf(-0.99999994f, val);
        z[d] = 1.41421356237f * erfinvf(val);
    }

    float s0 = sv[3 * p], s1 = sv[3 * p + 1], s2 = sv[3 * p + 2];
    float u0 = T[0] * s0 + T[1] * s1 + T[2] * s2;
    float u1 = T[3] * s0 + T[4] * s1 + T[5] * s2;
    float u2 = T[6] * s0 + T[7] * s1 + T[8] * s2;

    g_state[3 * p + 0] = u0 + z[0] * l00 + z[1] * l10 + z[2] * l20;
    g_state[3 * p + 1] = u1 + z[1] * l11 + z[2] * l21;
    g_state[3 * p + 2] = u2 + z[2] * l22;
}

// ---------------- kernel B: w[a] = sum_b (x[a,b] - F[b].s_a)^2 ------------
// EXACT round-5 inner form. Fires the PDL trigger EARLY (so k_cat Phase A
// overlaps this kernel), and signals actual completion of its g_invw stores
// through g_wdone (threadfence + atomic), which k_cat polls before Phase B.
__global__ void k_weights(const float* __restrict__ x, const float* __restrict__ F)
{
    cudaTriggerProgrammaticLaunchCompletion();

    int warp = threadIdx.x >> 5, lane = threadIdx.x & 31;
    int a0 = blockIdx.x * 16 + warp * 2;
    int a1 = a0 + 1;

    float s00 = g_state[3 * a0], s01 = g_state[3 * a0 + 1], s02 = g_state[3 * a0 + 2];
    float s10 = g_state[3 * a1], s11 = g_state[3 * a1 + 1], s12 = g_state[3 * a1 + 2];

    const float4* x0 = reinterpret_cast<const float4*>(x + (size_t)a0 * NP);
    const float4* x1 = reinterpret_cast<const float4*>(x + (size_t)a1 * NP);
    const float4* Fv = reinterpret_cast<const float4*>(F);

    float acc0 = 0.0f, acc1 = 0.0f;
#pragma unroll 4
    for (int it = 0; it < NP / 128; ++it) {
        int b4 = it * 32 + lane;
        float4 xa = __ldg(x0 + b4);
        float4 xb = __ldg(x1 + b4);
        float4 f0 = __ldg(Fv + 3 * b4 + 0);
        float4 f1 = __ldg(Fv + 3 * b4 + 1);
        float4 f2 = __ldg(Fv + 3 * b4 + 2);
        float p0 = f0.x * s00 + f0.y * s01 + f0.z * s02;
        float p1 = f0.w * s00 + f1.x * s01 + f1.y * s02;
        float p2 = f1.z * s00 + f1.w * s01 + f2.x * s02;
        float p3 = f2.y * s00 + f2.z * s01 + f2.w * s02;
        float q0 = f0.x * s10 + f0.y * s11 + f0.z * s12;
        float q1 = f0.w * s10 + f1.x * s11 + f1.y * s12;
        float q2 = f1.z * s10 + f1.w * s11 + f2.x * s12;
        float q3 = f2.y * s10 + f2.z * s11 + f2.w * s12;
        float d;
        d = xa.x - p0; acc0 = fmaf(d, d, acc0);
        d = xa.y - p1; acc0 = fmaf(d, d, acc0);
        d = xa.z - p2; acc0 = fmaf(d, d, acc0);
        d = xa.w - p3; acc0 = fmaf(d, d, acc0);
        d = xb.x - q0; acc1 = fmaf(d, d, acc1);
        d = xb.y - q1; acc1 = fmaf(d, d, acc1);
        d = xb.z - q2; acc1 = fmaf(d, d, acc1);
        d = xb.w - q3; acc1 = fmaf(d, d, acc1);
    }
#pragma unroll
    for (int o = 16; o; o >>= 1) {
        acc0 += __shfl_down_sync(0xffffffffu, acc0, o);
        acc1 += __shfl_down_sync(0xffffffffu, acc1, o);
    }
    if (lane == 0) {
        g_invw[a0] = 1.0f / acc0;
        g_invw[a1] = 1.0f / acc1;
    }
    __syncthreads();                 // all warps' stores issued
    if (threadIdx.x == 0) {
        __threadfence();             // make g_invw visible device-wide
        atomicAdd(&g_wdone, 1);      // signal this block's completion
    }
}

// ---------------- kernel C: categorical + fused mean-of-gathered ----------
// Phase A: all 32 threefry words per thread into registers (no global reads)
//          — pipe-balanced threefry; overlaps k_weights via PDL.
// Gate:    poll g_wdone == NWB (k_weights really done), acquire fence.
// Phase B: identical selection arithmetic to the validated round-7 kernel.
__global__ void k_cat(uint32_t kc0, uint32_t kc1, float* __restrict__ out)
{
    const int row = blockIdx.x;
    const int t = threadIdx.x;
    const float INF = __int_as_float(0x7f800000);
    int lane = t & 31, warp = t >> 5;

    __shared__ float shv[8];
    __shared__ int   shi[8];
    __shared__ float sthr;

    const uint32_t base = (uint32_t)row * (uint32_t)NP;

    // ---- Phase A: PRNG only (independent of k_weights output) ----
    uint32_t B[32];
#pragma unroll
    for (int k = 0; k < 8; ++k) {
        uint32_t n0 = base + (uint32_t)((k << 10) + 4 * t);
        B[4 * k + 0] = tf32_bal(kc0, kc1, n0 + 0u);
        B[4 * k + 1] = tf32_bal(kc0, kc1, n0 + 1u);
        B[4 * k + 2] = tf32_bal(kc0, kc1, n0 + 2u);
        B[4 * k + 3] = tf32_bal(kc0, kc1, n0 + 3u);
    }

    // ---- Gate: wait for k_weights' g_invw to be complete & visible ----
    cudaGridDependencySynchronize();          // PDL bookkeeping (cheap)
    if (t == 0) {
        while (atomicAdd(&g_wdone, 0) < NWB)  // k_weights blocks all signaled?
            __nanosleep(64);
    }
    __syncthreads();
    __threadfence();                          // acquire: invw reads see stores

    const float4* invw4 = reinterpret_cast<const float4*>(g_invw);

    // ---- prologue: k=0, j = 4t..4t+3, all exact; seeds the threshold ----
    float mv = INF;
    int   mi = 0;
    {
        int j0 = 4 * t;
        float4 iw = __ldg(invw4 + t);
        float v0 = exact_v(B[0], iw.x);
        float v1 = exact_v(B[1], iw.y);
        float v2 = exact_v(B[2], iw.z);
        float v3 = exact_v(B[3], iw.w);
        mv = v0; mi = j0;
        if (v1 < mv) { mv = v1; mi = j0 + 1; }
        if (v2 < mv) { mv = v2; mi = j0 + 2; }
        if (v3 < mv) { mv = v3; mi = j0 + 3; }

        float tv = mv;
#pragma unroll
        for (int o = 16; o; o >>= 1)
            tv = fminf(tv, __shfl_xor_sync(0xffffffffu, tv, o));
        if (lane == 0) shv[warp] = tv;
        __syncthreads();
        if (t == 0) {
            float m = shv[0];
#pragma unroll
            for (int wq = 1; wq < 8; ++wq) m = fminf(m, shv[wq]);
            sthr = m * 1.000004f;   // fudged static threshold
        }
        __syncthreads();
    }
    const float thr2 = sthr;
    __syncthreads();   // shv reused below; everyone read sthr

    // ---- main loop: k = 1..7, 4 elems/thread/iter with screen ----
#pragma unroll 1
    for (int k = 1; k < 8; ++k) {
        int j0 = (k << 10) + 4 * t;
        float4 iw = __ldg(invw4 + (k << 8) + t);
        uint32_t b0 = B[4 * k + 0];
        uint32_t b1 = B[4 * k + 1];
        uint32_t b2 = B[4 * k + 2];
        uint32_t b3 = B[4 * k + 3];

        uint32_t t0 = __umulhi(b0, 0x00800000u) + 0x3f800000u;
        uint32_t t1 = __umulhi(b1, 0x00800000u) + 0x3f800000u;
        uint32_t t2 = __umulhi(b2, 0x00800000u) + 0x3f800000u;
        uint32_t t3 = __umulhi(b3, 0x00800000u) + 0x3f800000u;
        float s0 = 2.0f - __uint_as_float(t0);   // = 1-u, exact
        float s1 = 2.0f - __uint_as_float(t1);
        float s2 = 2.0f - __uint_as_float(t2);
        float s3 = 2.0f - __uint_as_float(t3);

        if (__ballot_sync(0xffffffffu, s0 * iw.x <= thr2)) {
            float v = exact_v(b0, iw.x);
            if (v < mv) { mv = v; mi = j0; }
        }
        if (__ballot_sync(0xffffffffu, s1 * iw.y <= thr2)) {
            float v = exact_v(b1, iw.y);
            if (v < mv) { mv = v; mi = j0 + 1; }
        }
        if (__ballot_sync(0xffffffffu, s2 * iw.z <= thr2)) {
            float v = exact_v(b2, iw.z);
            if (v < mv) { mv = v; mi = j0 + 2; }
        }
        if (__ballot_sync(0xffffffffu, s3 * iw.w <= thr2)) {
            float v = exact_v(b3, iw.w);
            if (v < mv) { mv = v; mi = j0 + 3; }
        }
    }

    // ---- block argmin reduce (value, then lower index on exact ties) ----
#pragma unroll
    for (int o = 16; o; o >>= 1) {
        float ov = __shfl_down_sync(0xffffffffu, mv, o);
        int   oi = __shfl_down_sync(0xffffffffu, mi, o);
        if (ov < mv || (ov == mv && oi < mi)) { mv = ov; mi = oi; }
    }
    if (lane == 0) { shv[warp] = mv; shi[warp] = mi; }
    __syncthreads();
    if (warp == 0) {
        float v2 = (lane < 8) ? shv[lane] : INF;
        int   i2 = (lane < 8) ? shi[lane] : 0x7fffffff;
#pragma unroll
        for (int o = 4; o; o >>= 1) {
            float ov = __shfl_down_sync(0xffffffffu, v2, o);
            int   oi = __shfl_down_sync(0xffffffffu, i2, o);
            if (ov < v2 || (ov == v2 && oi < i2)) { v2 = ov; i2 = oi; }
        }
        if (lane == 0) {
            atomicAdd(&g_sum[0], g_state[3 * i2 + 0]);
            atomicAdd(&g_sum[1], g_state[3 * i2 + 1]);
            atomicAdd(&g_sum[2], g_state[3 * i2 + 2]);
            __threadfence();
            if (atomicAdd(&g_done, 1) == (int)gridDim.x - 1) {
                out[0] = g_sum[0] * (1.0f / NP);
                out[1] = g_sum[1] * (1.0f / NP);
                out[2] = g_sum[2] * (1.0f / NP);
            }
        }
    }
}

// ---------------- host: key derivation (fold-like split) ------------------
static void h_tf(uint32_t k0, uint32_t k1, uint32_t x0, uint32_t x1,
                 uint32_t& y0, uint32_t& y1)
{
    uint32_t k2 = k0 ^ k1 ^ 0x1BD11BDAu;
    x0 += k0; x1 += k1;
    const int R0[4] = {13, 15, 26, 6}, R1[4] = {17, 29, 16, 24};
    const int* RS[5] = {R0, R1, R0, R1, R0};
    const uint32_t ks[3] = {k0, k1, k2};
    for (int g = 0; g < 5; ++g) {
        for (int q = 0; q < 4; ++q) {
            x0 += x1;
            int r = RS[g][q];
            x1 = (x1 << r) | (x1 >> (32 - r));
            x1 ^= x0;
        }
        x0 += ks[(g + 1) % 3];
        x1 += ks[(g + 2) % 3] + (uint32_t)(g + 1);
    }
    y0 = x0; y1 = x1;
}

extern "C" void kernel_launch(void* const* d_in, const int* in_sizes, int n_in,
                              void* d_out, int out_size)
{
    const float* x  = (const float*)d_in[0];  // inputs (1, C, P)
    const float* sv = (const float*)d_in[1];  // state_vector (P, 3)
    const float* T  = (const float*)d_in[2];  // transition (3, 3)
    const float* Q  = (const float*)d_in[3];  // process noise cov (3, 3)
    const float* F  = (const float*)d_in[4];  // forward_matrix (C, 3)

    uint32_t kn0, kn1, kc0, kc1;
    h_tf(0u, 42u, 0u, 0u, kn0, kn1);  // k_noise
    h_tf(0u, 42u, 0u, 1u, kc0, kc1);  // k_cat

    k_state  <<<NP / 256, 256>>>(sv, T, Q, kn0, kn1);
    k_weights<<<NWB, 256>>>(x, F);

    // k_cat with Programmatic Dependent Launch: Phase A (pure PRNG) overlaps
    // k_weights; the g_wdone flag (not the PDL sync) guards the invw reads.
    cudaLaunchConfig_t cfg = {};
    cfg.gridDim = dim3(NP, 1, 1);
    cfg.blockDim = dim3(256, 1, 1);
    cudaLaunchAttribute attrs[1];
    attrs[0].id = cudaLaunchAttributeProgrammaticStreamSerialization;
    attrs[0].val.programmaticStreamSerializationAllowed = 1;
    cfg.attrs = attrs;
    cfg.numAttrs = 1;
    cudaError_t e = cudaLaunchKernelEx(&cfg, k_cat, kc0, kc1, (float*)d_out);
    if (e != cudaSuccess) {
        // Fallback: plain serialized launch (gate passes immediately).
        k_cat<<<NP, 256>>>(kc0, kc1, (float*)d_out);
    }
}

// round 11
// speedup vs baseline: 1.0150x; 1.0150x over previous
#include <cuda_runtime.h>
#include <cstdint>
#include <math.h>

#define NP 8192            // particles == channels
#define NWB (NP / 16)      // k_weights grid size (512 blocks)

// ---------------- device scratch (no allocations allowed) ----------------
__device__ float g_state[NP * 3];
__device__ float g_invw[NP];
__device__ float g_F0[NP], g_F1[NP], g_F2[NP];  // planar transpose of F
__device__ float g_sum[3];
__device__ int   g_done;
__device__ int   g_wdone;   // k_weights completion counter (software flag)

// ---------------- threefry2x32 (JAX rotation schedule) -------------------
// All-SHF form (round-9 validated; mul-wide variant measured slower).
__device__ __forceinline__ uint32_t tf32(uint32_t k0, uint32_t k1, uint32_t n)
{
    uint32_t k2 = k0 ^ k1 ^ 0x1BD11BDAu;
    uint32_t x0 = k0;          // 0 + ks[0]
    uint32_t x1 = n + k1;      // n + ks[1]
#define TFR(r) { x0 += x1; x1 = __funnelshift_l(x1, x1, (r)); x1 ^= x0; }
    TFR(13) TFR(15) TFR(26) TFR(6)
    x0 += k1; x1 += k2 + 1u;
    TFR(17) TFR(29) TFR(16) TFR(24)
    x0 += k2; x1 += k0 + 2u;
    TFR(13) TFR(15) TFR(26) TFR(6)
    x0 += k0; x1 += k1 + 3u;
    TFR(17) TFR(29) TFR(16) TFR(24)
    x0 += k1; x1 += k2 + 4u;
    TFR(13) TFR(15) TFR(26) TFR(6)
    x0 += k2; x1 += k0 + 5u;
#undef TFR
    return x0 ^ x1;
}

// exact v for the categorical: v = (-logf(u)) * invw, identical arithmetic
// to the validated round-1 kernel (bitwise-stable selection).
__device__ __forceinline__ float exact_v(uint32_t b, float invw)
{
    uint32_t tbits = __umulhi(b, 0x00800000u) + 0x3f800000u; // 1 + (b>>9)*2^-23
    float f = __uint_as_float(tbits) - 1.0f;
    float u = fmaxf(f, 1.17549435e-38f);
    float e = -logf(u);
    return e * invw;
}

// ---------------- kernel A: state transition + noise + F transpose -------
__global__ void k_state(const float* __restrict__ sv,
                        const float* __restrict__ T,
                        const float* __restrict__ Q,
                        const float* __restrict__ F,
                        uint32_t kn0, uint32_t kn1)
{
    int p = blockIdx.x * blockDim.x + threadIdx.x;
    if (p < 3) g_sum[p] = 0.0f;   // reset accumulators each launch (graph replay)
    if (p == 3) g_done = 0;
    if (p == 4) g_wdone = 0;
    if (p >= NP) return;

    // planar transpose of F (for lane-contiguous loads in k_weights)
    g_F0[p] = F[3 * p + 0];
    g_F1[p] = F[3 * p + 1];
    g_F2[p] = F[3 * p + 2];

    float l00 = sqrtf(Q[0]);
    float l10 = Q[3] / l00, l20 = Q[6] / l00;
    float l11 = sqrtf(Q[4] - l10 * l10);
    float l21 = (Q[7] - l20 * l10) / l11;
    float l22 = sqrtf(Q[8] - l20 * l20 - l21 * l21);

    float z[3];
#pragma unroll
    for (int d = 0; d < 3; ++d) {
        uint32_t b = tf32(kn0, kn1, (uint32_t)(3 * p + d));
        float f = __uint_as_float(0x3f800000u | (b >> 9)) - 1.0f;
        float val = __fadd_rn(__fmul_rn(f, 2.0f), -0.99999994f);
        val = fmaxf(-0.99999994f, val);
        z[d] = 1.41421356237f * erfinvf(val);
    }

    float s0 = sv[3 * p], s1 = sv[3 * p + 1], s2 = sv[3 * p + 2];
    float u0 = T[0] * s0 + T[1] * s1 + T[2] * s2;
    float u1 = T[3] * s0 + T[4] * s1 + T[5] * s2;
    float u2 = T[6] * s0 + T[7] * s1 + T[8] * s2;

    g_state[3 * p + 0] = u0 + z[0] * l00 + z[1] * l10 + z[2] * l20;
    g_state[3 * p + 1] = u1 + z[1] * l11 + z[2] * l21;
    g_state[3 * p + 2] = u2 + z[2] * l22;
}

// ---------------- kernel B: w[a] = sum_b (x[a,b] - F[b].s_a)^2 ------------
// 2 rows per warp (round-5 structure) with PLANAR F loads: each of the three
// F loads is lane-contiguous float4 (4 wavefronts instead of 12), dropping
// the iteration cost from 44 to 20 L1 wavefronts -> DRAM-stream bound.
__global__ void k_weights(const float* __restrict__ x)
{
    cudaTriggerProgrammaticLaunchCompletion();

    int warp = threadIdx.x >> 5, lane = threadIdx.x & 31;
    int a0 = blockIdx.x * 16 + warp * 2;
    int a1 = a0 + 1;

    float s00 = g_state[3 * a0], s01 = g_state[3 * a0 + 1], s02 = g_state[3 * a0 + 2];
    float s10 = g_state[3 * a1], s11 = g_state[3 * a1 + 1], s12 = g_state[3 * a1 + 2];

    const float4* x0 = reinterpret_cast<const float4*>(x + (size_t)a0 * NP);
    const float4* x1 = reinterpret_cast<const float4*>(x + (size_t)a1 * NP);
    const float4* F0 = reinterpret_cast<const float4*>(g_F0);
    const float4* F1 = reinterpret_cast<const float4*>(g_F1);
    const float4* F2 = reinterpret_cast<const float4*>(g_F2);

    float acc0 = 0.0f, acc1 = 0.0f;
#pragma unroll 4
    for (int it = 0; it < NP / 128; ++it) {
        int b4 = it * 32 + lane;
        float4 xa = __ldg(x0 + b4);
        float4 xb = __ldg(x1 + b4);
        float4 fa = __ldg(F0 + b4);   // component 0 of F rows 4b4..4b4+3
        float4 fb = __ldg(F1 + b4);   // component 1
        float4 fc = __ldg(F2 + b4);   // component 2
        float p0 = fa.x * s00 + fb.x * s01 + fc.x * s02;
        float p1 = fa.y * s00 + fb.y * s01 + fc.y * s02;
        float p2 = fa.z * s00 + fb.z * s01 + fc.z * s02;
        float p3 = fa.w * s00 + fb.w * s01 + fc.w * s02;
        float q0 = fa.x * s10 + fb.x * s11 + fc.x * s12;
        float q1 = fa.y * s10 + fb.y * s11 + fc.y * s12;
        float q2 = fa.z * s10 + fb.z * s11 + fc.z * s12;
        float q3 = fa.w * s10 + fb.w * s11 + fc.w * s12;
        float d;
        d = xa.x - p0; acc0 = fmaf(d, d, acc0);
        d = xa.y - p1; acc0 = fmaf(d, d, acc0);
        d = xa.z - p2; acc0 = fmaf(d, d, acc0);
        d = xa.w - p3; acc0 = fmaf(d, d, acc0);
        d = xb.x - q0; acc1 = fmaf(d, d, acc1);
        d = xb.y - q1; acc1 = fmaf(d, d, acc1);
        d = xb.z - q2; acc1 = fmaf(d, d, acc1);
        d = xb.w - q3; acc1 = fmaf(d, d, acc1);
    }
#pragma unroll
    for (int o = 16; o; o >>= 1) {
        acc0 += __shfl_down_sync(0xffffffffu, acc0, o);
        acc1 += __shfl_down_sync(0xffffffffu, acc1, o);
    }
    if (lane == 0) {
        g_invw[a0] = 1.0f / acc0;
        g_invw[a1] = 1.0f / acc1;
    }
    __syncthreads();                 // all warps' stores issued
    if (threadIdx.x == 0) {
        __threadfence();             // make g_invw visible device-wide
        atomicAdd(&g_wdone, 1);      // signal this block's completion
    }
}

// ---------------- kernel C: categorical + fused mean-of-gathered ----------
// Phase A: all 32 threefry words per thread into registers (no global reads)
//          — overlaps k_weights via programmatic dependent launch.
// Gate:    poll g_wdone == NWB (k_weights really done), acquire fence.
// Phase B: identical selection arithmetic to the validated round-7 kernel.
__global__ void k_cat(uint32_t kc0, uint32_t kc1, float* __restrict__ out)
{
    const int row = blockIdx.x;
    const int t = threadIdx.x;
    const float INF = __int_as_float(0x7f800000);
    int lane = t & 31, warp = t >> 5;

    __shared__ float shv[8];
    __shared__ int   shi[8];
    __shared__ float sthr;

    const uint32_t base = (uint32_t)row * (uint32_t)NP;

    // ---- Phase A: PRNG only (independent of k_weights output) ----
    uint32_t B[32];
#pragma unroll
    for (int k = 0; k < 8; ++k) {
        uint32_t n0 = base + (uint32_t)((k << 10) + 4 * t);
        B[4 * k + 0] = tf32(kc0, kc1, n0 + 0u);
        B[4 * k + 1] = tf32(kc0, kc1, n0 + 1u);
        B[4 * k + 2] = tf32(kc0, kc1, n0 + 2u);
        B[4 * k + 3] = tf32(kc0, kc1, n0 + 3u);
    }

    // ---- Gate: wait for k_weights' g_invw to be complete & visible ----
    cudaGridDependencySynchronize();          // PDL bookkeeping (cheap)
    if (t == 0) {
        while (atomicAdd(&g_wdone, 0) < NWB)  // k_weights blocks all signaled?
            __nanosleep(64);
    }
    __syncthreads();
    __threadfence();                          // acquire: invw reads see stores

    const float4* invw4 = reinterpret_cast<const float4*>(g_invw);

    // ---- prologue: k=0, j = 4t..4t+3, all exact; seeds the threshold ----
    float mv = INF;
    int   mi = 0;
    {
        int j0 = 4 * t;
        float4 iw = __ldg(invw4 + t);
        float v0 = exact_v(B[0], iw.x);
        float v1 = exact_v(B[1], iw.y);
        float v2 = exact_v(B[2], iw.z);
        float v3 = exact_v(B[3], iw.w);
        mv = v0; mi = j0;
        if (v1 < mv) { mv = v1; mi = j0 + 1; }
        if (v2 < mv) { mv = v2; mi = j0 + 2; }
        if (v3 < mv) { mv = v3; mi = j0 + 3; }

        float tv = mv;
#pragma unroll
        for (int o = 16; o; o >>= 1)
            tv = fminf(tv, __shfl_xor_sync(0xffffffffu, tv, o));
        if (lane == 0) shv[warp] = tv;
        __syncthreads();
        if (t == 0) {
            float m = shv[0];
#pragma unroll
            for (int wq = 1; wq < 8; ++wq) m = fminf(m, shv[wq]);
            sthr = m * 1.000004f;   // fudged static threshold
        }
        __syncthreads();
    }
    const float thr2 = sthr;
    __syncthreads();   // shv reused below; everyone read sthr

    // ---- main loop: k = 1..7, 4 elems/thread/iter with screen ----
#pragma unroll 1
    for (int k = 1; k < 8; ++k) {
        int j0 = (k << 10) + 4 * t;
        float4 iw = __ldg(invw4 + (k << 8) + t);
        uint32_t b0 = B[4 * k + 0];
        uint32_t b1 = B[4 * k + 1];
        uint32_t b2 = B[4 * k + 2];
        uint32_t b3 = B[4 * k + 3];

        uint32_t t0 = __umulhi(b0, 0x00800000u) + 0x3f800000u;
        uint32_t t1 = __umulhi(b1, 0x00800000u) + 0x3f800000u;
        uint32_t t2 = __umulhi(b2, 0x00800000u) + 0x3f800000u;
        uint32_t t3 = __umulhi(b3, 0x00800000u) + 0x3f800000u;
        float s0 = 2.0f - __uint_as_float(t0);   // = 1-u, exact
        float s1 = 2.0f - __uint_as_float(t1);
        float s2 = 2.0f - __uint_as_float(t2);
        float s3 = 2.0f - __uint_as_float(t3);

        if (__ballot_sync(0xffffffffu, s0 * iw.x <= thr2)) {
            float v = exact_v(b0, iw.x);
            if (v < mv) { mv = v; mi = j0; }
        }
        if (__ballot_sync(0xffffffffu, s1 * iw.y <= thr2)) {
            float v = exact_v(b1, iw.y);
            if (v < mv) { mv = v; mi = j0 + 1; }
        }
        if (__ballot_sync(0xffffffffu, s2 * iw.z <= thr2)) {
            float v = exact_v(b2, iw.z);
            if (v < mv) { mv = v; mi = j0 + 2; }
        }
        if (__ballot_sync(0xffffffffu, s3 * iw.w <= thr2)) {
            float v = exact_v(b3, iw.w);
            if (v < mv) { mv = v; mi = j0 + 3; }
        }
    }

    // ---- block argmin reduce (value, then lower index on exact ties) ----
#pragma unroll
    for (int o = 16; o; o >>= 1) {
        float ov = __shfl_down_sync(0xffffffffu, mv, o);
        int   oi = __shfl_down_sync(0xffffffffu, mi, o);
        if (ov < mv || (ov == mv && oi < mi)) { mv = ov; mi = oi; }
    }
    if (lane == 0) { shv[warp] = mv; shi[warp] = mi; }
    __syncthreads();
    if (warp == 0) {
        float v2 = (lane < 8) ? shv[lane] : INF;
        int   i2 = (lane < 8) ? shi[lane] : 0x7fffffff;
#pragma unroll
        for (int o = 4; o; o >>= 1) {
            float ov = __shfl_down_sync(0xffffffffu, v2, o);
            int   oi = __shfl_down_sync(0xffffffffu, i2, o);
            if (ov < v2 || (ov == v2 && oi < i2)) { v2 = ov; i2 = oi; }
        }
        if (lane == 0) {
            atomicAdd(&g_sum[0], g_state[3 * i2 + 0]);
            atomicAdd(&g_sum[1], g_state[3 * i2 + 1]);
            atomicAdd(&g_sum[2], g_state[3 * i2 + 2]);
            __threadfence();
            if (atomicAdd(&g_done, 1) == (int)gridDim.x - 1) {
                out[0] = g_sum[0] * (1.0f / NP);
                out[1] = g_sum[1] * (1.0f / NP);
                out[2] = g_sum[2] * (1.0f / NP);
            }
        }
    }
}

// ---------------- host: key derivation (fold-like split) ------------------
static void h_tf(uint32_t k0, uint32_t k1, uint32_t x0, uint32_t x1,
                 uint32_t& y0, uint32_t& y1)
{
    uint32_t k2 = k0 ^ k1 ^ 0x1BD11BDAu;
    x0 += k0; x1 += k1;
    const int R0[4] = {13, 15, 26, 6}, R1[4] = {17, 29, 16, 24};
    const int* RS[5] = {R0, R1, R0, R1, R0};
    const uint32_t ks[3] = {k0, k1, k2};
    for (int g = 0; g < 5; ++g) {
        for (int q = 0; q < 4; ++q) {
            x0 += x1;
            int r = RS[g][q];
            x1 = (x1 << r) | (x1 >> (32 - r));
            x1 ^= x0;
        }
        x0 += ks[(g + 1) % 3];
        x1 += ks[(g + 2) % 3] + (uint32_t)(g + 1);
    }
    y0 = x0; y1 = x1;
}

extern "C" void kernel_launch(void* const* d_in, const int* in_sizes, int n_in,
                              void* d_out, int out_size)
{
    const float* x  = (const float*)d_in[0];  // inputs (1, C, P)
    const float* sv = (const float*)d_in[1];  // state_vector (P, 3)
    const float* T  = (const float*)d_in[2];  // transition (3, 3)
    const float* Q  = (const float*)d_in[3];  // process noise cov (3, 3)
    const float* F  = (const float*)d_in[4];  // forward_matrix (C, 3)

    uint32_t kn0, kn1, kc0, kc1;
    h_tf(0u, 42u, 0u, 0u, kn0, kn1);  // k_noise
    h_tf(0u, 42u, 0u, 1u, kc0, kc1);  // k_cat

    k_state  <<<NP / 256, 256>>>(sv, T, Q, F, kn0, kn1);
    k_weights<<<NWB, 256>>>(x);

    // k_cat with Programmatic Dependent Launch: Phase A (pure PRNG) overlaps
    // k_weights; the g_wdone flag (not the PDL sync) guards the invw reads.
    cudaLaunchConfig_t cfg = {};
    cfg.gridDim = dim3(NP, 1, 1);
    cfg.blockDim = dim3(256, 1, 1);
    cudaLaunchAttribute attrs[1];
    attrs[0].id = cudaLaunchAttributeProgrammaticStreamSerialization;
    attrs[0].val.programmaticStreamSerializationAllowed = 1;
    cfg.attrs = attrs;
    cfg.numAttrs = 1;
    cudaError_t e = cudaLaunchKernelEx(&cfg, k_cat, kc0, kc1, (float*)d_out);
    if (e != cudaSuccess) {
        // Fallback: plain serialized launch (gate passes immediately).
        k_cat<<<NP, 256>>>(kc0, kc1, (float*)d_out);
    }
}

// round 12
// speedup vs baseline: 1.0406x; 1.0252x over previous
#include <cuda_runtime.h>
#include <cstdint>
#include <math.h>

#define NP 8192            // particles == channels
#define NWB (NP / 16)      // k_weights grid size (512 blocks)

// ---------------- device scratch (no allocations allowed) ----------------
__device__ float g_state[NP * 3];
__device__ float g_invw[NP];
__device__ float g_sum[3];
__device__ int   g_done;
__device__ int   g_wdone;   // k_weights completion counter (software flag)

// ---------------- threefry2x32 (JAX rotation schedule) -------------------
// All-SHF form (validated; mul-wide variant measured slower in round 10).
__device__ __forceinline__ uint32_t tf32(uint32_t k0, uint32_t k1, uint32_t n)
{
    uint32_t k2 = k0 ^ k1 ^ 0x1BD11BDAu;
    uint32_t x0 = k0;          // 0 + ks[0]
    uint32_t x1 = n + k1;      // n + ks[1]
#define TFR(r) { x0 += x1; x1 = __funnelshift_l(x1, x1, (r)); x1 ^= x0; }
    TFR(13) TFR(15) TFR(26) TFR(6)
    x0 += k1; x1 += k2 + 1u;
    TFR(17) TFR(29) TFR(16) TFR(24)
    x0 += k2; x1 += k0 + 2u;
    TFR(13) TFR(15) TFR(26) TFR(6)
    x0 += k0; x1 += k1 + 3u;
    TFR(17) TFR(29) TFR(16) TFR(24)
    x0 += k1; x1 += k2 + 4u;
    TFR(13) TFR(15) TFR(26) TFR(6)
    x0 += k2; x1 += k0 + 5u;
#undef TFR
    return x0 ^ x1;
}

// exact v for the categorical: v = (-logf(u)) * invw, identical arithmetic
// to the validated round-1 kernel (bitwise-stable selection).
__device__ __forceinline__ float exact_v(uint32_t b, float invw)
{
    uint32_t tbits = __umulhi(b, 0x00800000u) + 0x3f800000u; // 1 + (b>>9)*2^-23
    float f = __uint_as_float(tbits) - 1.0f;
    float u = fmaxf(f, 1.17549435e-38f);
    float e = -logf(u);
    return e * invw;
}

// ---------------- kernel A: state transition + process noise -------------
// 128-thread blocks (64 blocks): latency-bound erfinv chain spread over 2x
// the SMs vs the old 32x256 config.
__global__ void k_state(const float* __restrict__ sv,
                        const float* __restrict__ T,
                        const float* __restrict__ Q,
                        uint32_t kn0, uint32_t kn1)
{
    int p = blockIdx.x * 128 + threadIdx.x;
    if (p < 3) g_sum[p] = 0.0f;   // reset accumulators each launch (graph replay)
    if (p == 3) g_done = 0;
    if (p == 4) g_wdone = 0;
    if (p >= NP) return;

    float l00 = sqrtf(Q[0]);
    float l10 = Q[3] / l00, l20 = Q[6] / l00;
    float l11 = sqrtf(Q[4] - l10 * l10);
    float l21 = (Q[7] - l20 * l10) / l11;
    float l22 = sqrtf(Q[8] - l20 * l20 - l21 * l21);

    float z[3];
#pragma unroll
    for (int d = 0; d < 3; ++d) {
        uint32_t b = tf32(kn0, kn1, (uint32_t)(3 * p + d));
        float f = __uint_as_float(0x3f800000u | (b >> 9)) - 1.0f;
        float val = __fadd_rn(__fmul_rn(f, 2.0f), -0.99999994f);
        val = fmaxf(-0.99999994f, val);
        z[d] = 1.41421356237f * erfinvf(val);
    }

    float s0 = sv[3 * p], s1 = sv[3 * p + 1], s2 = sv[3 * p + 2];
    float u0 = T[0] * s0 + T[1] * s1 + T[2] * s2;
    float u1 = T[3] * s0 + T[4] * s1 + T[5] * s2;
    float u2 = T[6] * s0 + T[7] * s1 + T[8] * s2;

    g_state[3 * p + 0] = u0 + z[0] * l00 + z[1] * l10 + z[2] * l20;
    g_state[3 * p + 1] = u1 + z[1] * l11 + z[2] * l21;
    g_state[3 * p + 2] = u2 + z[2] * l22;
}

// ---------------- kernel B: w[a] = sum_b (x[a,b] - F[b].s_a)^2 ------------
// EXACT round-9 form (measured best): 2 rows per warp, interleaved-F __ldg
// float4 loads. Early PDL trigger + g_wdone completion flag.
__global__ void k_weights(const float* __restrict__ x, const float* __restrict__ F)
{
    cudaTriggerProgrammaticLaunchCompletion();

    int warp = threadIdx.x >> 5, lane = threadIdx.x & 31;
    int a0 = blockIdx.x * 16 + warp * 2;
    int a1 = a0 + 1;

    float s00 = g_state[3 * a0], s01 = g_state[3 * a0 + 1], s02 = g_state[3 * a0 + 2];
    float s10 = g_state[3 * a1], s11 = g_state[3 * a1 + 1], s12 = g_state[3 * a1 + 2];

    const float4* x0 = reinterpret_cast<const float4*>(x + (size_t)a0 * NP);
    const float4* x1 = reinterpret_cast<const float4*>(x + (size_t)a1 * NP);
    const float4* Fv = reinterpret_cast<const float4*>(F);

    float acc0 = 0.0f, acc1 = 0.0f;
#pragma unroll 4
    for (int it = 0; it < NP / 128; ++it) {
        int b4 = it * 32 + lane;
        float4 xa = __ldg(x0 + b4);
        float4 xb = __ldg(x1 + b4);
        float4 f0 = __ldg(Fv + 3 * b4 + 0);
        float4 f1 = __ldg(Fv + 3 * b4 + 1);
        float4 f2 = __ldg(Fv + 3 * b4 + 2);
        float p0 = f0.x * s00 + f0.y * s01 + f0.z * s02;
        float p1 = f0.w * s00 + f1.x * s01 + f1.y * s02;
        float p2 = f1.z * s00 + f1.w * s01 + f2.x * s02;
        float p3 = f2.y * s00 + f2.z * s01 + f2.w * s02;
        float q0 = f0.x * s10 + f0.y * s11 + f0.z * s12;
        float q1 = f0.w * s10 + f1.x * s11 + f1.y * s12;
        float q2 = f1.z * s10 + f1.w * s11 + f2.x * s12;
        float q3 = f2.y * s10 + f2.z * s11 + f2.w * s12;
        float d;
        d = xa.x - p0; acc0 = fmaf(d, d, acc0);
        d = xa.y - p1; acc0 = fmaf(d, d, acc0);
        d = xa.z - p2; acc0 = fmaf(d, d, acc0);
        d = xa.w - p3; acc0 = fmaf(d, d, acc0);
        d = xb.x - q0; acc1 = fmaf(d, d, acc1);
        d = xb.y - q1; acc1 = fmaf(d, d, acc1);
        d = xb.z - q2; acc1 = fmaf(d, d, acc1);
        d = xb.w - q3; acc1 = fmaf(d, d, acc1);
    }
#pragma unroll
    for (int o = 16; o; o >>= 1) {
        acc0 += __shfl_down_sync(0xffffffffu, acc0, o);
        acc1 += __shfl_down_sync(0xffffffffu, acc1, o);
    }
    if (lane == 0) {
        g_invw[a0] = 1.0f / acc0;
        g_invw[a1] = 1.0f / acc1;
    }
    __syncthreads();                 // all warps' stores issued
    if (threadIdx.x == 0) {
        __threadfence();             // make g_invw visible device-wide
        atomicAdd(&g_wdone, 1);      // signal this block's completion
    }
}

// ---------------- kernel C: categorical + fused mean-of-gathered ----------
// Phase A: all 32 threefry words per thread into registers.
// Gate:    poll g_wdone == NWB, acquire fence.
// Phase B: static-threshold screen, now ONE ballot per 4 elements via a
//          fminf-tree. Skipped groups have all four fl(s_i*iw_i) > thr2 ->
//          all true v_i > row min (safe). Fired groups evaluate all four
//          exactly — exact evaluation is always selection-safe.
__global__ void k_cat(uint32_t kc0, uint32_t kc1, float* __restrict__ out)
{
    const int row = blockIdx.x;
    const int t = threadIdx.x;
    const float INF = __int_as_float(0x7f800000);
    int lane = t & 31, warp = t >> 5;

    __shared__ float shv[8];
    __shared__ int   shi[8];
    __shared__ float sthr;

    const uint32_t base = (uint32_t)row * (uint32_t)NP;

    // ---- Phase A: PRNG only (independent of k_weights output) ----
    uint32_t B[32];
#pragma unroll
    for (int k = 0; k < 8; ++k) {
        uint32_t n0 = base + (uint32_t)((k << 10) + 4 * t);
        B[4 * k + 0] = tf32(kc0, kc1, n0 + 0u);
        B[4 * k + 1] = tf32(kc0, kc1, n0 + 1u);
        B[4 * k + 2] = tf32(kc0, kc1, n0 + 2u);
        B[4 * k + 3] = tf32(kc0, kc1, n0 + 3u);
    }

    // ---- Gate: wait for k_weights' g_invw to be complete & visible ----
    cudaGridDependencySynchronize();          // PDL bookkeeping (cheap)
    if (t == 0) {
        while (atomicAdd(&g_wdone, 0) < NWB)  // k_weights blocks all signaled?
            __nanosleep(64);
    }
    __syncthreads();
    __threadfence();                          // acquire: invw reads see stores

    const float4* invw4 = reinterpret_cast<const float4*>(g_invw);

    // ---- prologue: k=0, j = 4t..4t+3, all exact; seeds the threshold ----
    float mv = INF;
    int   mi = 0;
    {
        int j0 = 4 * t;
        float4 iw = __ldg(invw4 + t);
        float v0 = exact_v(B[0], iw.x);
        float v1 = exact_v(B[1], iw.y);
        float v2 = exact_v(B[2], iw.z);
        float v3 = exact_v(B[3], iw.w);
        mv = v0; mi = j0;
        if (v1 < mv) { mv = v1; mi = j0 + 1; }
        if (v2 < mv) { mv = v2; mi = j0 + 2; }
        if (v3 < mv) { mv = v3; mi = j0 + 3; }

        float tv = mv;
#pragma unroll
        for (int o = 16; o; o >>= 1)
            tv = fminf(tv, __shfl_xor_sync(0xffffffffu, tv, o));
        if (lane == 0) shv[warp] = tv;
        __syncthreads();
        if (t == 0) {
            float m = shv[0];
#pragma unroll
            for (int wq = 1; wq < 8; ++wq) m = fminf(m, shv[wq]);
            sthr = m * 1.000004f;   // fudged static threshold
        }
        __syncthreads();
    }
    const float thr2 = sthr;
    __syncthreads();   // shv reused below; everyone read sthr

    // ---- main loop: k = 1..7, 4 elems/thread/iter, 1 ballot per group ----
#pragma unroll 1
    for (int k = 1; k < 8; ++k) {
        int j0 = (k << 10) + 4 * t;
        float4 iw = __ldg(invw4 + (k << 8) + t);
        uint32_t b0 = B[4 * k + 0];
        uint32_t b1 = B[4 * k + 1];
        uint32_t b2 = B[4 * k + 2];
        uint32_t b3 = B[4 * k + 3];

        uint32_t t0 = __umulhi(b0, 0x00800000u) + 0x3f800000u;
        uint32_t t1 = __umulhi(b1, 0x00800000u) + 0x3f800000u;
        uint32_t t2 = __umulhi(b2, 0x00800000u) + 0x3f800000u;
        uint32_t t3 = __umulhi(b3, 0x00800000u) + 0x3f800000u;
        float e0 = (2.0f - __uint_as_float(t0)) * iw.x;   // s = 1-u, exact
        float e1 = (2.0f - __uint_as_float(t1)) * iw.y;
        float e2 = (2.0f - __uint_as_float(t2)) * iw.z;
        float e3 = (2.0f - __uint_as_float(t3)) * iw.w;
        float emin = fminf(fminf(e0, e1), fminf(e2, e3));

        if (__ballot_sync(0xffffffffu, emin <= thr2)) {
            float v0 = exact_v(b0, iw.x);
            if (v0 < mv) { mv = v0; mi = j0; }
            float v1 = exact_v(b1, iw.y);
            if (v1 < mv) { mv = v1; mi = j0 + 1; }
            float v2 = exact_v(b2, iw.z);
            if (v2 < mv) { mv = v2; mi = j0 + 2; }
            float v3 = exact_v(b3, iw.w);
            if (v3 < mv) { mv = v3; mi = j0 + 3; }
        }
    }

    // ---- block argmin reduce (value, then lower index on exact ties) ----
#pragma unroll
    for (int o = 16; o; o >>= 1) {
        float ov = __shfl_down_sync(0xffffffffu, mv, o);
        int   oi = __shfl_down_sync(0xffffffffu, mi, o);
        if (ov < mv || (ov == mv && oi < mi)) { mv = ov; mi = oi; }
    }
    if (lane == 0) { shv[warp] = mv; shi[warp] = mi; }
    __syncthreads();
    if (warp == 0) {
        float v2 = (lane < 8) ? shv[lane] : INF;
        int   i2 = (lane < 8) ? shi[lane] : 0x7fffffff;
#pragma unroll
        for (int o = 4; o; o >>= 1) {
            float ov = __shfl_down_sync(0xffffffffu, v2, o);
            int   oi = __shfl_down_sync(0xffffffffu, i2, o);
            if (ov < v2 || (ov == v2 && oi < i2)) { v2 = ov; i2 = oi; }
        }
        if (lane == 0) {
            atomicAdd(&g_sum[0], g_state[3 * i2 + 0]);
            atomicAdd(&g_sum[1], g_state[3 * i2 + 1]);
            atomicAdd(&g_sum[2], g_state[3 * i2 + 2]);
            __threadfence();
            if (atomicAdd(&g_done, 1) == (int)gridDim.x - 1) {
                out[0] = g_sum[0] * (1.0f / NP);
                out[1] = g_sum[1] * (1.0f / NP);
                out[2] = g_sum[2] * (1.0f / NP);
            }
        }
    }
}

// ---------------- host: key derivation (fold-like split) ------------------
static void h_tf(uint32_t k0, uint32_t k1, uint32_t x0, uint32_t x1,
                 uint32_t& y0, uint32_t& y1)
{
    uint32_t k2 = k0 ^ k1 ^ 0x1BD11BDAu;
    x0 += k0; x1 += k1;
    const int R0[4] = {13, 15, 26, 6}, R1[4] = {17, 29, 16, 24};
    const int* RS[5] = {R0, R1, R0, R1, R0};
    const uint32_t ks[3] = {k0, k1, k2};
    for (int g = 0; g < 5; ++g) {
        for (int q = 0; q < 4; ++q) {
            x0 += x1;
            int r = RS[g][q];
            x1 = (x1 << r) | (x1 >> (32 - r));
            x1 ^= x0;
        }
        x0 += ks[(g + 1) % 3];
        x1 += ks[(g + 2) % 3] + (uint32_t)(g + 1);
    }
    y0 = x0; y1 = x1;
}

extern "C" void kernel_launch(void* const* d_in, const int* in_sizes, int n_in,
                              void* d_out, int out_size)
{
    const float* x  = (const float*)d_in[0];  // inputs (1, C, P)
    const float* sv = (const float*)d_in[1];  // state_vector (P, 3)
    const float* T  = (const float*)d_in[2];  // transition (3, 3)
    const float* Q  = (const float*)d_in[3];  // process noise cov (3, 3)
    const float* F  = (const float*)d_in[4];  // forward_matrix (C, 3)

    uint32_t kn0, kn1, kc0, kc1;
    h_tf(0u, 42u, 0u, 0u, kn0, kn1);  // k_noise
    h_tf(0u, 42u, 0u, 1u, kc0, kc1);  // k_cat

    k_state  <<<NP / 128, 128>>>(sv, T, Q, kn0, kn1);
    k_weights<<<NWB, 256>>>(x, F);

    // k_cat with Programmatic Dependent Launch: Phase A (pure PRNG) overlaps
    // k_weights; the g_wdone flag (not the PDL sync) guards the invw reads.
    cudaLaunchConfig_t cfg = {};
    cfg.gridDim = dim3(NP, 1, 1);
    cfg.blockDim = dim3(256, 1, 1);
    cudaLaunchAttribute attrs[1];
    attrs[0].id = cudaLaunchAttributeProgrammaticStreamSerialization;
    attrs[0].val.programmaticStreamSerializationAllowed = 1;
    cfg.attrs = attrs;
    cfg.numAttrs = 1;
    cudaError_t e = cudaLaunchKernelEx(&cfg, k_cat, kc0, kc1, (float*)d_out);
    if (e != cudaSuccess) {
        // Fallback: plain serialized launch (gate passes immediately).
        k_cat<<<NP, 256>>>(kc0, kc1, (float*)d_out);
    }
}